// round 7
// baseline (speedup 1.0000x reference)
#include <cuda_runtime.h>
#include <math.h>

// Problem constants (fixed by setup_inputs)
#define BSZ   16
#define QN    900
#define CN    80
#define TN    1600
#define GS    3
#define NQ    (BSZ * QN)        // 14400
#define NROWS (NQ / GS)         // 4800 output rows
#define RPB   (QN / GS)         // 300 rows per batch

// Scratch (allocation-free rule: __device__ globals)
// cc table TRANSPOSED: g_ccT[c*NQ + n] = 2 * focal_cost(n, c)  -> consecutive n per column label
__device__ float  g_ccT[CN * NQ];
// query structs (SoA, all coords pre-scaled by 5; areas by 25)
__device__ float4 g_qA[NQ];     // (5cx, 5cy, 5w, 5h)
__device__ float4 g_qB[NQ];     // (5x0, 5y0, 5x1, 5y1)
__device__ float  g_qC[NQ];     // 25*area
// target structs
__device__ float4 g_tA[TN];     // (5cx, 5cy, 5w, 5h)
__device__ float4 g_tB[TN];     // (5x0, 5y0, 5x1, 5y1)
__device__ float2 g_tC[TN];     // (25*area, label-as-float-bits)

__device__ __forceinline__ float focal_cc2(float x) {
    float p   = 1.f / (1.f + __expf(-x));
    float om  = 1.f - p;
    float pos = 0.5f * om * om * (-__logf(p + 1e-8f));   // 2 * 0.25
    float neg = 1.5f * p  * p  * (-__logf(om + 1e-8f));  // 2 * 0.75
    return pos - neg;
}

// ---------------- fused prep ----------------
#define CCB 1125   // (NQ*CN/4)/256 blocks for the cc table
#define BXB 57     // ceil(NQ/256) blocks for boxes

__global__ __launch_bounds__(256) void prep_kernel(const float4* __restrict__ logits4,
                                                   const float*  __restrict__ qb,
                                                   const float*  __restrict__ tb,
                                                   const int*    __restrict__ tl) {
    int b = blockIdx.x;
    if (b < CCB) {
        int i = b * 256 + threadIdx.x;      // covers (n, c0..c0+3)
        float4 x = logits4[i];
        int n  = i / 20;
        int c0 = (i % 20) * 4;
        g_ccT[(c0+0) * NQ + n] = focal_cc2(x.x);
        g_ccT[(c0+1) * NQ + n] = focal_cc2(x.y);
        g_ccT[(c0+2) * NQ + n] = focal_cc2(x.z);
        g_ccT[(c0+3) * NQ + n] = focal_cc2(x.w);
    } else {
        int i = (b - CCB) * 256 + threadIdx.x;
        if (i < NQ) {
            float cx = qb[i*4+0], cy = qb[i*4+1], w = qb[i*4+2], h = qb[i*4+3];
            float x0 = cx - 0.5f*w, y0 = cy - 0.5f*h;
            float x1 = cx + 0.5f*w, y1 = cy + 0.5f*h;
            float area = (x1 - x0) * (y1 - y0);          // reference rounding path, then scale
            g_qA[i] = make_float4(5.f*cx, 5.f*cy, 5.f*w, 5.f*h);
            g_qB[i] = make_float4(5.f*x0, 5.f*y0, 5.f*x1, 5.f*y1);
            g_qC[i] = 25.f * area;
        }
        if (i < TN) {
            float cx = tb[i*4+0], cy = tb[i*4+1], w = tb[i*4+2], h = tb[i*4+3];
            float x0 = cx - 0.5f*w, y0 = cy - 0.5f*h;
            float x1 = cx + 0.5f*w, y1 = cy + 0.5f*h;
            float area = (x1 - x0) * (y1 - y0);
            g_tA[i] = make_float4(5.f*cx, 5.f*cy, 5.f*w, 5.f*h);
            g_tB[i] = make_float4(5.f*x0, 5.f*y0, 5.f*x1, 5.f*y1);
            g_tC[i] = make_float2(25.f * area, __int_as_float(tl[i]));
        }
    }
}

// ---------------- main: fused cost + group-max, 2 adjacent columns per thread ----------------
#define THR  160     // 5 warps; block covers 320 adjacent columns
#define RCH  6       // output rows per block (fully unrolled); grid = 5 x 800 = 4000 blocks
#define NQC  (RCH * GS)   // 18 queries per chunk

__device__ __forceinline__ float rcp_approx(float x) {
    float r; asm("rcp.approx.f32 %0, %1;" : "=f"(r) : "f"(x)); return r;
}

// All coords 5x-scaled, areas 25x; GIoU ratios are scale-invariant.
__device__ __forceinline__ float pair_cost(const float4 qA, const float4 qB, const float qC,
                                           const float4 tA, const float4 tB, const float tC,
                                           const float cc2) {
    // L1 (x5 pre-scaled): weight folded
    float l1 = fabsf(qA.x - tA.x) + fabsf(qA.y - tA.y)
             + fabsf(qA.z - tA.z) + fabsf(qA.w - tA.w);
    // intersection (5x coords -> 25x areas)
    float ltx = fmaxf(qB.x, tB.x), lty = fmaxf(qB.y, tB.y);
    float rbx = fminf(qB.z, tB.z), rby = fminf(qB.w, tB.w);
    float dx = rbx - ltx,          dy = rby - lty;
    float wx = fmaxf(dx, 0.f),     wy = fmaxf(dy, 0.f);
    float inter = wx * wy;
    float uni = (qC + tC) - inter;
    // enclosing box: ewx = 5qw + 5tw - dx (max(a,b) = a+b-min(a,b))
    float ewx = (qA.z + tA.z) - dx;
    float ewy = (qA.w + tA.w) - dy;
    float earea = ewx * ewy;
    // cost = l1 + cc2 + 2*(1 - uni/earea - inter/uni)
    float ru = rcp_approx(uni);
    float re = rcp_approx(earea);
    float s  = __fmaf_rn(-uni,   re, 1.0f);
    s        = __fmaf_rn(-inter, ru, s);
    return __fmaf_rn(2.f, s, l1 + cc2);
}

__global__ __launch_bounds__(THR) void cost_kernel(float* __restrict__ out) {
    __shared__ float4 shA[NQC];
    __shared__ float4 shB[NQC];
    __shared__ float  shC[NQC];

    const int t0 = (blockIdx.x * THR + threadIdx.x) * 2;   // adjacent target columns t0, t0+1
    const int r0 = blockIdx.y * RCH;                       // first output row of this chunk
    const int nstart = (r0 / RPB) * QN + (r0 % RPB) * GS;  // 300 % RCH == 0: no batch crossing

    {
        int tid = threadIdx.x;
        if (tid < NQC)                    shA[tid]          = g_qA[nstart + tid];
        else if (tid < 2*NQC)             shB[tid - NQC]    = g_qB[nstart + tid - NQC];
        else if (tid < 3*NQC)             shC[tid - 2*NQC]  = g_qC[nstart + tid - 2*NQC];
    }
    __syncthreads();

    // target data -> registers (held for the whole chunk)
    const float4 tA0 = g_tA[t0],   tA1 = g_tA[t0+1];
    const float4 tB0 = g_tB[t0],   tB1 = g_tB[t0+1];
    const float2 tC0 = g_tC[t0],   tC1 = g_tC[t0+1];
    // transposed cc: 18 consecutive floats per column label (L1-resident)
    const float* ccp0 = g_ccT + (size_t)__float_as_int(tC0.y) * NQ + nstart;
    const float* ccp1 = g_ccT + (size_t)__float_as_int(tC1.y) * NQ + nstart;

    float* op = out + (size_t)r0 * TN + t0;

    #pragma unroll
    for (int rr = 0; rr < RCH; rr++) {
        float m0, m1;
        #pragma unroll
        for (int g = 0; g < GS; g++) {
            const int qi = rr*3 + g;
            const float4 qA = shA[qi];
            const float4 qB = shB[qi];
            const float  qC = shC[qi];
            const float cc0 = __ldg(ccp0 + qi);   // consecutive, immediate offsets
            const float cc1 = __ldg(ccp1 + qi);
            float c0 = pair_cost(qA, qB, qC, tA0, tB0, tC0.x, cc0);
            float c1 = pair_cost(qA, qB, qC, tA1, tB1, tC1.x, cc1);
            if (g == 0) { m0 = c0; m1 = c1; }
            else        { m0 = fmaxf(m0, c0); m1 = fmaxf(m1, c1); }
        }
        *reinterpret_cast<float2*>(op + rr * TN) = make_float2(m0, m1);
    }
}

extern "C" void kernel_launch(void* const* d_in, const int* in_sizes, int n_in,
                              void* d_out, int out_size) {
    const float* logits  = (const float*)d_in[0];  // [16,900,80]
    const float* pboxes  = (const float*)d_in[1];  // [16,900,4]
    const int*   tlabels = (const int*)  d_in[2];  // [1600]
    const float* tboxes  = (const float*)d_in[3];  // [1600,4]
    (void)in_sizes; (void)n_in; (void)out_size;

    prep_kernel<<<CCB + BXB, 256>>>((const float4*)logits, pboxes, tboxes, tlabels);
    cost_kernel<<<dim3(800 / THR, NROWS / RCH), THR>>>((float*)d_out);
}

// round 8
// speedup vs baseline: 1.9802x; 1.9802x over previous
#include <cuda_runtime.h>
#include <math.h>

// Problem constants (fixed by setup_inputs)
#define BSZ   16
#define QN    900
#define CN    80
#define TN    1600
#define GS    3
#define NQ    (BSZ * QN)        // 14400
#define NROWS (NQ / GS)         // 4800 output rows
#define RPB   (QN / GS)         // 300 rows per batch

// Scratch (allocation-free rule: __device__ globals)
__device__ float  g_cc[NQ * CN];   // 2x focal class cost, [n][c] (labels = fast axis!)
__device__ float4 g_qA[NQ];        // (5cx, 5cy, 5w, 5h)
__device__ float4 g_qB[NQ];        // (5x0, 5y0, 5x1, 5y1)
__device__ float  g_qC[NQ];        // 25*area
__device__ float4 g_tA[TN];        // (5cx, 5cy, 5w, 5h)
__device__ float4 g_tB[TN];        // (5x0, 5y0, 5x1, 5y1)
__device__ float2 g_tC[TN];        // (25*area, label-as-float-bits)

__device__ __forceinline__ float focal_cc2(float x) {
    float p   = 1.f / (1.f + __expf(-x));
    float om  = 1.f - p;
    float pos = 0.5f * om * om * (-__logf(p + 1e-8f));   // 2 * 0.25
    float neg = 1.5f * p  * p  * (-__logf(om + 1e-8f));  // 2 * 0.75
    return pos - neg;
}

// ---------------- fused prep ----------------
#define CCB 1125   // (NQ*CN/4)/256 blocks for the cc table
#define BXB 57     // ceil(NQ/256) blocks for boxes

__global__ __launch_bounds__(256) void prep_kernel(const float4* __restrict__ logits4,
                                                   const float*  __restrict__ qb,
                                                   const float*  __restrict__ tb,
                                                   const int*    __restrict__ tl) {
    int b = blockIdx.x;
    if (b < CCB) {
        int i = b * 256 + threadIdx.x;
        float4 x = logits4[i];
        float4 r;
        r.x = focal_cc2(x.x); r.y = focal_cc2(x.y);
        r.z = focal_cc2(x.z); r.w = focal_cc2(x.w);
        reinterpret_cast<float4*>(g_cc)[i] = r;
    } else {
        int i = (b - CCB) * 256 + threadIdx.x;
        if (i < NQ) {
            float cx = qb[i*4+0], cy = qb[i*4+1], w = qb[i*4+2], h = qb[i*4+3];
            float x0 = cx - 0.5f*w, y0 = cy - 0.5f*h;
            float x1 = cx + 0.5f*w, y1 = cy + 0.5f*h;
            float area = (x1 - x0) * (y1 - y0);          // reference rounding path, then scale
            g_qA[i] = make_float4(5.f*cx, 5.f*cy, 5.f*w, 5.f*h);
            g_qB[i] = make_float4(5.f*x0, 5.f*y0, 5.f*x1, 5.f*y1);
            g_qC[i] = 25.f * area;
        }
        if (i < TN) {
            float cx = tb[i*4+0], cy = tb[i*4+1], w = tb[i*4+2], h = tb[i*4+3];
            float x0 = cx - 0.5f*w, y0 = cy - 0.5f*h;
            float x1 = cx + 0.5f*w, y1 = cy + 0.5f*h;
            float area = (x1 - x0) * (y1 - y0);
            g_tA[i] = make_float4(5.f*cx, 5.f*cy, 5.f*w, 5.f*h);
            g_tB[i] = make_float4(5.f*x0, 5.f*y0, 5.f*x1, 5.f*y1);
            g_tC[i] = make_float2(25.f * area, __int_as_float(tl[i]));
        }
    }
}

// ---------------- main: fused cost + group-max, 2 adjacent columns, cc fully prefetched ----------------
#define THR  160     // 5 warps; block covers 320 adjacent columns
#define RCH  5       // output rows per block; 15 queries; grid = 5 x 960 = 4800 blocks
#define NQC  (RCH * GS)   // 15 queries per chunk

__device__ __forceinline__ float rcp_approx(float x) {
    float r; asm("rcp.approx.f32 %0, %1;" : "=f"(r) : "f"(x)); return r;
}

// All coords 5x-scaled, areas 25x; GIoU ratios are scale-invariant.
__device__ __forceinline__ float pair_cost(const float4 qA, const float4 qB, const float qC,
                                           const float4 tA, const float4 tB, const float tC,
                                           const float cc2) {
    float l1 = fabsf(qA.x - tA.x) + fabsf(qA.y - tA.y)
             + fabsf(qA.z - tA.z) + fabsf(qA.w - tA.w);
    float ltx = fmaxf(qB.x, tB.x), lty = fmaxf(qB.y, tB.y);
    float rbx = fminf(qB.z, tB.z), rby = fminf(qB.w, tB.w);
    float dx = rbx - ltx,          dy = rby - lty;
    float wx = fmaxf(dx, 0.f),     wy = fmaxf(dy, 0.f);
    float inter = wx * wy;
    float uni = (qC + tC) - inter;
    float ewx = (qA.z + tA.z) - dx;      // max(a,b) = a+b-min(a,b)
    float ewy = (qA.w + tA.w) - dy;
    float earea = ewx * ewy;
    float ru = rcp_approx(uni);
    float re = rcp_approx(earea);
    float s  = __fmaf_rn(-uni,   re, 1.0f);
    s        = __fmaf_rn(-inter, ru, s);
    return __fmaf_rn(2.f, s, l1 + cc2);
}

__global__ __launch_bounds__(THR) void cost_kernel(float* __restrict__ out) {
    __shared__ float4 shA[NQC];
    __shared__ float4 shB[NQC];
    __shared__ float  shC[NQC];

    const int t0 = (blockIdx.x * THR + threadIdx.x) * 2;   // adjacent target columns t0, t0+1
    const int r0 = blockIdx.y * RCH;                       // first output row of this chunk
    const int nstart = (r0 / RPB) * QN + (r0 % RPB) * GS;  // 300 % RCH == 0: no batch crossing

    {
        int tid = threadIdx.x;
        if (tid < NQC)            shA[tid]         = g_qA[nstart + tid];
        else if (tid < 2*NQC)     shB[tid - NQC]   = g_qB[nstart + tid - NQC];
        else if (tid < 3*NQC)     shC[tid - 2*NQC] = g_qC[nstart + tid - 2*NQC];
    }
    __syncthreads();

    // target data -> registers (held for the whole chunk)
    const float4 tA0 = g_tA[t0],   tA1 = g_tA[t0+1];
    const float4 tB0 = g_tB[t0],   tB1 = g_tB[t0+1];
    const float2 tC0 = g_tC[t0],   tC1 = g_tC[t0+1];

    // prefetch ALL class costs for the chunk (labels fast axis -> 3 lines/warp/load)
    const float* ccp0 = g_cc + nstart * CN + __float_as_int(tC0.y);
    const float* ccp1 = g_cc + nstart * CN + __float_as_int(tC1.y);
    float cc0v[NQC], cc1v[NQC];
    #pragma unroll
    for (int qi = 0; qi < NQC; qi++) {
        cc0v[qi] = __ldg(ccp0 + qi * CN);   // immediate offsets, MLP = 30
        cc1v[qi] = __ldg(ccp1 + qi * CN);
    }

    float* op = out + (size_t)r0 * TN + t0;

    #pragma unroll
    for (int rr = 0; rr < RCH; rr++) {
        float m0, m1;
        #pragma unroll
        for (int g = 0; g < GS; g++) {
            const int qi = rr*3 + g;
            const float4 qA = shA[qi];
            const float4 qB = shB[qi];
            const float  qC = shC[qi];
            float c0 = pair_cost(qA, qB, qC, tA0, tB0, tC0.x, cc0v[qi]);
            float c1 = pair_cost(qA, qB, qC, tA1, tB1, tC1.x, cc1v[qi]);
            if (g == 0) { m0 = c0; m1 = c1; }
            else        { m0 = fmaxf(m0, c0); m1 = fmaxf(m1, c1); }
        }
        *reinterpret_cast<float2*>(op + rr * TN) = make_float2(m0, m1);
    }
}

extern "C" void kernel_launch(void* const* d_in, const int* in_sizes, int n_in,
                              void* d_out, int out_size) {
    const float* logits  = (const float*)d_in[0];  // [16,900,80]
    const float* pboxes  = (const float*)d_in[1];  // [16,900,4]
    const int*   tlabels = (const int*)  d_in[2];  // [1600]
    const float* tboxes  = (const float*)d_in[3];  // [1600,4]
    (void)in_sizes; (void)n_in; (void)out_size;

    prep_kernel<<<CCB + BXB, 256>>>((const float4*)logits, pboxes, tboxes, tlabels);
    cost_kernel<<<dim3(TN / (THR*2), NROWS / RCH), THR>>>((float*)d_out);
}